// round 1
// baseline (speedup 1.0000x reference)
#include <cuda_runtime.h>
#include <math.h>

// Problem constants (fixed by the dataset)
#define BATCH 256
#define LL    16
#define UU    512
#define NB    4            // batches per CTA
#define NTHR  256          // 2 output units per thread (UU / NTHR = 2)
#define NCTA  (BATCH / NB) // 64

struct SM {
    float4 h[UU];              // current hidden, [u] = {b0,b1,b2,b3}   (8 KB)
    float4 states[LL][UU];     // previous-row hidden per column        (128 KB)
    float  winh[2][UU];        // W_in_h rows (one-hot lookup)          (4 KB)
    float  winv[2][UU];        //                                        (4 KB)
    float  bcarry[UU];         //                                        (2 KB)
    float  wout[UU][2];        //                                        (4 KB)
    float  z[NB][2];           // per-cell logits
    float  logp[NB];           // running log-prob
    float  bout0, bout1;
    int    xs[NB][LL * LL];    // spin lattice for this CTA's batches   (4 KB)
};

__device__ __forceinline__ unsigned long long pk2(float lo, float hi) {
    unsigned long long r;
    asm("mov.b64 %0, {%1, %2};" : "=l"(r) : "f"(lo), "f"(hi));
    return r;
}
__device__ __forceinline__ void upk2(unsigned long long v, float& lo, float& hi) {
    asm("mov.b64 {%0, %1}, %2;" : "=f"(lo), "=f"(hi) : "l"(v));
}
// packed dual fp32 FMA (sm_100+): acc.{lo,hi} += a.{lo,hi} * b.{lo,hi}
__device__ __forceinline__ void fma2(unsigned long long& acc,
                                     unsigned long long a, unsigned long long b) {
    asm("fma.rn.f32x2 %0, %1, %2, %0;" : "+l"(acc) : "l"(a), "l"(b));
}

__global__ void __launch_bounds__(NTHR, 1)
rnn2d_kernel(const int* __restrict__ x,
             const float* __restrict__ Winh, const float* __restrict__ Winv,
             const float* __restrict__ Wch,  const float* __restrict__ bch,
             const float* __restrict__ Wcv,
             const float* __restrict__ Wout, const float* __restrict__ bout,
             float* __restrict__ out)
{
    extern __shared__ char smraw[];
    SM& sm = *reinterpret_cast<SM*>(smraw);
    const int tid = threadIdx.x;
    const int b0  = blockIdx.x * NB;

    // ---- prologue: stage small operands + this CTA's spins into smem ----
    for (int idx = tid; idx < 2 * UU; idx += NTHR) {
        ((float*)sm.winh)[idx] = Winh[idx];
        ((float*)sm.winv)[idx] = Winv[idx];
        ((float*)sm.wout)[idx] = Wout[idx];
    }
    for (int idx = tid; idx < UU; idx += NTHR) sm.bcarry[idx] = bch[idx];
    for (int idx = tid; idx < NB * LL * LL; idx += NTHR)
        ((int*)sm.xs)[idx] = x[b0 * LL * LL + idx];
    if (tid == 0) { sm.bout0 = bout[0]; sm.bout1 = bout[1]; }
    if (tid < NB) sm.logp[tid] = 0.f;
    __syncthreads();

    const int u0 = tid * 2;  // this thread's two output units: u0, u0+1
    const ulonglong2* __restrict__ hp = reinterpret_cast<const ulonglong2*>(sm.h);

    for (int i = 0; i < LL; ++i) {
        const int d = (i & 1) ? -1 : 1;  // boustrophedon direction
        for (int j = 0; j < LL; ++j) {
            const int c = (d == 1) ? j : (LL - 1 - j);  // spatial column

            // ---- init: bias + one-hot input rows (per batch) ----
            float v0[NB], v1[NB];
            {
                const float bb0 = sm.bcarry[u0];
                const float bb1 = sm.bcarry[u0 + 1];
#pragma unroll
                for (int b = 0; b < NB; ++b) { v0[b] = bb0; v1[b] = bb1; }
            }
            if (j > 0) {  // left-in-scan-order neighbor one-hot
                const int cp = c - d;
#pragma unroll
                for (int b = 0; b < NB; ++b) {
                    const int s = sm.xs[b][i * LL + cp];
                    v0[b] += sm.winh[s][u0];
                    v1[b] += sm.winh[s][u0 + 1];
                }
            }
            if (i > 0) {  // above-cell one-hot
#pragma unroll
                for (int b = 0; b < NB; ++b) {
                    const int s = sm.xs[b][(i - 1) * LL + c];
                    v0[b] += sm.winv[s][u0];
                    v1[b] += sm.winv[s][u0 + 1];
                }
            }
            unsigned long long a0p = pk2(v0[0], v0[1]), a0q = pk2(v0[2], v0[3]);
            unsigned long long a1p = pk2(v1[0], v1[1]), a1q = pk2(v1[2], v1[3]);

            // ---- h @ W_carry_h  (skip at scan start: h == 0) ----
            if (j > 0) {
                const float2* __restrict__ wp =
                    reinterpret_cast<const float2*>(Wch + u0);
#pragma unroll 8
                for (int k = 0; k < UU; ++k) {
                    const float2 w = wp[k * (UU / 2)];
                    const ulonglong2 hv = hp[k];  // {b0,b1},{b2,b3} broadcast
                    const unsigned long long wx = pk2(w.x, w.x);
                    const unsigned long long wy = pk2(w.y, w.y);
                    fma2(a0p, hv.x, wx); fma2(a0q, hv.y, wx);
                    fma2(a1p, hv.x, wy); fma2(a1q, hv.y, wy);
                }
            }
            // ---- cv @ W_carry_v (skip at row 0: states == 0) ----
            if (i > 0) {
                const float2* __restrict__ wp =
                    reinterpret_cast<const float2*>(Wcv + u0);
                const ulonglong2* __restrict__ sp =
                    reinterpret_cast<const ulonglong2*>(sm.states[c]);
#pragma unroll 8
                for (int k = 0; k < UU; ++k) {
                    const float2 w = wp[k * (UU / 2)];
                    const ulonglong2 sv = sp[k];
                    const unsigned long long wx = pk2(w.x, w.x);
                    const unsigned long long wy = pk2(w.y, w.y);
                    fma2(a0p, sv.x, wx); fma2(a0q, sv.y, wx);
                    fma2(a1p, sv.x, wy); fma2(a1q, sv.y, wy);
                }
            }

            // ---- elu ----
            float n0[NB], n1[NB];
            upk2(a0p, n0[0], n0[1]); upk2(a0q, n0[2], n0[3]);
            upk2(a1p, n1[0], n1[1]); upk2(a1q, n1[2], n1[3]);
#pragma unroll
            for (int b = 0; b < NB; ++b) {
                n0[b] = n0[b] > 0.f ? n0[b] : expm1f(n0[b]);
                n1[b] = n1[b] > 0.f ? n1[b] : expm1f(n1[b]);
            }

            __syncthreads();  // all reads of old h / states[c] complete
            {
                const float4 f0 = make_float4(n0[0], n0[1], n0[2], n0[3]);
                const float4 f1 = make_float4(n1[0], n1[1], n1[2], n1[3]);
                sm.h[u0] = f0;       sm.h[u0 + 1] = f1;
                sm.states[c][u0] = f0; sm.states[c][u0 + 1] = f1;
            }
            __syncthreads();  // new h visible to all

            // ---- logits: warp w handles (batch = w>>1, class = w&1) ----
            {
                const int w = tid >> 5, lane = tid & 31;
                const int bb = w >> 1, dd = w & 1;
                float z = 0.f;
#pragma unroll
                for (int u = lane; u < UU; u += 32)
                    z += ((const float*)&sm.h[u])[bb] * sm.wout[u][dd];
#pragma unroll
                for (int off = 16; off; off >>= 1)
                    z += __shfl_down_sync(0xffffffffu, z, off);
                if (lane == 0) sm.z[bb][dd] = z;
            }
            __syncthreads();

            if (tid < NB) {
                const float z0 = sm.z[tid][0] + sm.bout0;
                const float z1 = sm.z[tid][1] + sm.bout1;
                const int s = sm.xs[tid][i * LL + c];
                const float m = fmaxf(z0, z1);
                const float lse = m + logf(expf(z0 - m) + expf(z1 - m));
                sm.logp[tid] += (s ? z1 : z0) - lse;
            }
            // no barrier needed: next cell's writers cross 2 barriers first
        }
    }
    __syncthreads();
    if (tid < NB) out[b0 + tid] = sm.logp[tid];
}

extern "C" void kernel_launch(void* const* d_in, const int* in_sizes, int n_in,
                              void* d_out, int out_size)
{
    const int*   x    = (const int*)d_in[0];
    const float* Winh = (const float*)d_in[1];
    const float* Winv = (const float*)d_in[2];
    const float* Wch  = (const float*)d_in[3];
    const float* bch  = (const float*)d_in[4];
    const float* Wcv  = (const float*)d_in[5];
    const float* Wout = (const float*)d_in[6];
    const float* bout = (const float*)d_in[7];
    float* out = (float*)d_out;

    const int smem = (int)sizeof(SM);
    cudaFuncSetAttribute(rnn2d_kernel,
                         cudaFuncAttributeMaxDynamicSharedMemorySize, smem);
    rnn2d_kernel<<<NCTA, NTHR, smem>>>(x, Winh, Winv, Wch, bch, Wcv,
                                       Wout, bout, out);
}

// round 2
// speedup vs baseline: 1.7802x; 1.7802x over previous
#include <cuda_runtime.h>
#include <math.h>

#define BATCH 256
#define LL    16
#define UU    512
#define NB    4
#define NTHR  256
#define NCTA  (BATCH / NB)
#define CHUNK 16

struct SM {
    float4 h[UU];              // current hidden, [u] = {b0,b1,b2,b3}
    float4 states[LL][UU];     // previous-row hidden per column
    float4 red[128 * 4];       // cross-half partial sums
    float  winh[2][UU];
    float  winv[2][UU];
    float  bcarry[UU];
    float  wout[UU][2];
    float  z[NB][2];
    float  logp[NB];
    float  bout0, bout1;
    int    xs[NB][LL * LL];
};

__device__ __forceinline__ unsigned long long pk2(float lo, float hi) {
    unsigned long long r;
    asm("mov.b64 %0, {%1, %2};" : "=l"(r) : "f"(lo), "f"(hi));
    return r;
}
__device__ __forceinline__ void upk2(unsigned long long v, float& lo, float& hi) {
    asm("mov.b64 {%0, %1}, %2;" : "=f"(lo), "=f"(hi) : "l"(v));
}
__device__ __forceinline__ void fma2(unsigned long long& acc,
                                     unsigned long long a, unsigned long long b) {
    asm("fma.rn.f32x2 %0, %1, %2, %0;" : "+l"(acc) : "l"(a), "l"(b));
}

__global__ void __launch_bounds__(NTHR, 1)
rnn2d_kernel(const int* __restrict__ x,
             const float* __restrict__ Winh, const float* __restrict__ Winv,
             const float* __restrict__ Wch,  const float* __restrict__ bch,
             const float* __restrict__ Wcv,
             const float* __restrict__ Wout, const float* __restrict__ bout,
             float* __restrict__ out)
{
    extern __shared__ char smraw[];
    SM& sm = *reinterpret_cast<SM*>(smraw);
    const int tid = threadIdx.x;
    const int b0  = blockIdx.x * NB;

    // ---- prologue ----
    for (int idx = tid; idx < 2 * UU; idx += NTHR) {
        ((float*)sm.winh)[idx] = Winh[idx];
        ((float*)sm.winv)[idx] = Winv[idx];
        ((float*)sm.wout)[idx] = Wout[idx];
    }
    for (int idx = tid; idx < UU; idx += NTHR) sm.bcarry[idx] = bch[idx];
    for (int idx = tid; idx < NB * LL * LL; idx += NTHR)
        ((int*)sm.xs)[idx] = x[b0 * LL * LL + idx];
    // zero states (row 0 reads them unconditionally... actually guarded, but safe)
    {
        float4 zz = make_float4(0.f, 0.f, 0.f, 0.f);
        float4* st = &sm.states[0][0];
        for (int idx = tid; idx < LL * UU; idx += NTHR) st[idx] = zz;
    }
    if (tid == 0) { sm.bout0 = bout[0]; sm.bout1 = bout[1]; }
    if (tid < NB) sm.logp[tid] = 0.f;
    __syncthreads();

    const int half = tid >> 7;      // 0: h @ W_carry_h,  1: cv @ W_carry_v
    const int ut   = tid & 127;
    const int u0   = ut * 4;        // this thread's 4 output units
    const float4* __restrict__ Wp =
        reinterpret_cast<const float4*>(half ? Wcv : Wch) + ut;

    for (int i = 0; i < LL; ++i) {
        const int d = (i & 1) ? -1 : 1;
        for (int j = 0; j < LL; ++j) {
            const int c = (d == 1) ? j : (LL - 1 - j);

            unsigned long long A[4][2];
#pragma unroll
            for (int uu = 0; uu < 4; ++uu) { A[uu][0] = 0ull; A[uu][1] = 0ull; }

            const bool active = half ? (i > 0) : (j > 0);
            if (active) {
                const ulonglong2* __restrict__ vp = half
                    ? reinterpret_cast<const ulonglong2*>(sm.states[c])
                    : reinterpret_cast<const ulonglong2*>(sm.h);
#pragma unroll 1
                for (int kk = 0; kk < UU; kk += CHUNK) {
                    float4 w[CHUNK];
#pragma unroll
                    for (int t = 0; t < CHUNK; ++t)
                        w[t] = Wp[(kk + t) * (UU / 4)];
#pragma unroll
                    for (int t = 0; t < CHUNK; ++t) {
                        const ulonglong2 hv = vp[kk + t];   // 4 batch values, broadcast
                        const unsigned long long wa = pk2(w[t].x, w[t].x);
                        const unsigned long long wb = pk2(w[t].y, w[t].y);
                        const unsigned long long wc = pk2(w[t].z, w[t].z);
                        const unsigned long long wd = pk2(w[t].w, w[t].w);
                        fma2(A[0][0], hv.x, wa); fma2(A[0][1], hv.y, wa);
                        fma2(A[1][0], hv.x, wb); fma2(A[1][1], hv.y, wb);
                        fma2(A[2][0], hv.x, wc); fma2(A[2][1], hv.y, wc);
                        fma2(A[3][0], hv.x, wd); fma2(A[3][1], hv.y, wd);
                    }
                }
            }

            if (half) {  // publish cv-half partials
#pragma unroll
                for (int uu = 0; uu < 4; ++uu) {
                    float l0, h0, l1, h1;
                    upk2(A[uu][0], l0, h0); upk2(A[uu][1], l1, h1);
                    sm.red[ut * 4 + uu] = make_float4(l0, h0, l1, h1);
                }
            }
            __syncthreads();  // S1

            if (!half) {  // reduce + input terms + elu + write h/states
                int sh[NB], sv[NB];
                if (j > 0) {
                    const int cp = c - d;
#pragma unroll
                    for (int b = 0; b < NB; ++b) sh[b] = sm.xs[b][i * LL + cp];
                }
                if (i > 0) {
#pragma unroll
                    for (int b = 0; b < NB; ++b) sv[b] = sm.xs[b][(i - 1) * LL + c];
                }
#pragma unroll
                for (int uu = 0; uu < 4; ++uu) {
                    const int u = u0 + uu;
                    const float4 r = sm.red[ut * 4 + uu];
                    float m0, m1, m2, m3;
                    upk2(A[uu][0], m0, m1); upk2(A[uu][1], m2, m3);
                    float v[NB] = { m0 + r.x, m1 + r.y, m2 + r.z, m3 + r.w };
                    const float base = sm.bcarry[u];
#pragma unroll
                    for (int b = 0; b < NB; ++b) {
                        float t = v[b] + base;
                        if (j > 0) t += sm.winh[sh[b]][u];
                        if (i > 0) t += sm.winv[sv[b]][u];
                        v[b] = t > 0.f ? t : expm1f(t);
                    }
                    const float4 f = make_float4(v[0], v[1], v[2], v[3]);
                    sm.h[u] = f;
                    sm.states[c][u] = f;
                }
            }
            __syncthreads();  // S2

            // ---- logits: warp w handles (batch = w>>1, class = w&1) ----
            {
                const int w = tid >> 5, lane = tid & 31;
                const int bb = w >> 1, dd = w & 1;
                float z = 0.f;
#pragma unroll
                for (int u = lane; u < UU; u += 32)
                    z += ((const float*)&sm.h[u])[bb] * sm.wout[u][dd];
#pragma unroll
                for (int off = 16; off; off >>= 1)
                    z += __shfl_down_sync(0xffffffffu, z, off);
                if (lane == 0) sm.z[bb][dd] = z;
            }
            __syncthreads();  // S3

            if (tid < NB) {
                const float z0 = sm.z[tid][0] + sm.bout0;
                const float z1 = sm.z[tid][1] + sm.bout1;
                const int s = sm.xs[tid][i * LL + c];
                const float m = fmaxf(z0, z1);
                const float lse = m + logf(expf(z0 - m) + expf(z1 - m));
                sm.logp[tid] += (s ? z1 : z0) - lse;
            }
        }
    }
    __syncthreads();
    if (tid < NB) out[b0 + tid] = sm.logp[tid];
}

extern "C" void kernel_launch(void* const* d_in, const int* in_sizes, int n_in,
                              void* d_out, int out_size)
{
    const int*   x    = (const int*)d_in[0];
    const float* Winh = (const float*)d_in[1];
    const float* Winv = (const float*)d_in[2];
    const float* Wch  = (const float*)d_in[3];
    const float* bch  = (const float*)d_in[4];
    const float* Wcv  = (const float*)d_in[5];
    const float* Wout = (const float*)d_in[6];
    const float* bout = (const float*)d_in[7];
    float* out = (float*)d_out;

    const int smem = (int)sizeof(SM);
    cudaFuncSetAttribute(rnn2d_kernel,
                         cudaFuncAttributeMaxDynamicSharedMemorySize, smem);
    rnn2d_kernel<<<NCTA, NTHR, smem>>>(x, Winh, Winv, Wch, bch, Wcv,
                                       Wout, bout, out);
}